// round 8
// baseline (speedup 1.0000x reference)
#include <cuda_runtime.h>
#include <math.h>

// ---------------- static problem dims ----------------
#define T_N     200001
#define DD      16
#define HH      128
#define WIDW    256
#define LSIG    137
#define NSTEPS  100
#define NEVAL   200
#define G       16          // persistent CTAs (one w3 block each)
#define TPB     256

// ---------------- device scratch (no allocs allowed) ----------------
__device__ double g_lsbuf[NEVAL * LSIG];    // per-eval logsig row, pre-scaled by 1/interval (double)
__device__ double g_h1[WIDW];
__device__ double g_h2[WIDW];
__device__ double g_W[DD * HH];             // 2048: vf output (tangents)
__device__ double g_h1d[DD * WIDW];         // 4096
__device__ double g_h2d[DD * WIDW];         // 4096
__device__ double g_resP[G * HH];           // per-block partial field result
__device__ volatile unsigned g_flag[G * 8]; // epoch flags, padded 32B apart
__device__ int g_sel2048;                   // 0 => cand0 is l1_w, 1 => cand1 is l1_w
__device__ int g_sel256;                    // 0 => cand0 is b1,   1 => cand1 is b1

__device__ __forceinline__ int pair_index(int i, int j) {
    // row-major triu (i<j) pairs of D=16
    return i * (2 * DD - 1 - i) / 2 + (j - i - 1);
}

__device__ __forceinline__ double ldcg_d(const double* p) {
    return __longlong_as_double(__ldcg((const long long*)p));
}

__device__ __forceinline__ void grid_bar(unsigned ep, int tid, int cta) {
    __threadfence();
    __syncthreads();
    if (tid == 0) g_flag[cta * 8] = ep;
    if (tid < G) {
        while (g_flag[tid * 8] < ep) { }
        __threadfence();
    }
    __syncthreads();
}

// block-wide max|v| over n elements (fp32, for input disambiguation)
__device__ float block_maxabs(const float* p, int n) {
    __shared__ float red[256];
    float m = 0.f;
    for (int i = threadIdx.x; i < n; i += blockDim.x) m = fmaxf(m, fabsf(p[i]));
    red[threadIdx.x] = m;
    __syncthreads();
    for (int s = 128; s > 0; s >>= 1) {
        if (threadIdx.x < s) red[threadIdx.x] = fmaxf(red[threadIdx.x], red[threadIdx.x + s]);
        __syncthreads();
    }
    return red[0];
}

// ---------------- prep: per-eval t (exact fp32 accumulation), searchsorted idx,
//                  gather logsig row pre-scaled by 1/width in DOUBLE ----------------
__global__ void prep_kernel(const float* __restrict__ ts,
                            const float* __restrict__ logsig,
                            const float* __restrict__ c20a, const float* __restrict__ c20b,
                            const float* __restrict__ c25a, const float* __restrict__ c25b) {
    int e = blockIdx.x;

    if (e == NEVAL) {
        // l1_w bound 1/sqrt(16)=0.25 ; b3 bound 1/sqrt(256)=0.0625
        float m0 = block_maxabs(c20a, 2048);
        if (threadIdx.x == 0) g_sel2048 = (m0 > 0.07f) ? 0 : 1;
        return;
    }
    if (e == NEVAL + 1) {
        // b1 bound 1/sqrt(128)=0.0884 ; b2 bound 0.0625
        float m0 = block_maxabs(c25a, 256);
        if (threadIdx.x == 0) g_sel256 = (m0 > 0.0649f) ? 0 : 1;
        return;
    }

    __shared__ int    s_row;
    __shared__ double s_invw;
    if (threadIdx.x == 0) {
        if (e == 0) {
            for (int i = 0; i < G * 8; i++) g_flag[i] = 0u;
        }
        float ts0 = ts[0];
        float dt = (ts[T_N - 1] - ts0) / (float)NSTEPS;
        int s = e >> 1;
        float t = ts0;
        for (int i = 0; i < s; i++) t += dt;     // exact fp32 carry accumulation
        if (e & 1) t += dt;                       // k2 evaluated at t + dt

        // found = first j in [0, T_N-2] with ts[j+1] >= t, else T_N-1 (searchsorted left)
        int c = (int)(t * (float)(T_N - 1));
        int lo = c - 64; if (lo < 0) lo = 0;
        int hi = c + 64; if (hi > T_N - 2) hi = T_N - 2;
        int found = -1;
        if (lo == 0 || ts[lo] < t) {             // window-left validity
            for (int j = lo; j <= hi; j++) {
                if (ts[j + 1] >= t) { found = j; break; }
            }
            if (found < 0 && hi == T_N - 2) found = T_N - 1;
        }
        if (found < 0) {                          // safety: full binary search
            int a = 0, b = T_N - 2, res = T_N - 1;
            while (a <= b) {
                int m = (a + b) >> 1;
                if (ts[m + 1] >= t) { res = m; b = m - 1; } else a = m + 1;
            }
            found = res;
        }
        int idx = found + 1;
        if (idx > T_N - 1) idx = T_N - 1;
        s_row  = idx - 1;
        s_invw = 1.0 / ((double)ts[idx] - (double)ts[idx - 1]);
    }
    __syncthreads();
    int row = s_row; double invw = s_invw;
    for (int i = threadIdx.x; i < LSIG; i += blockDim.x)
        g_lsbuf[e * LSIG + i] = (double)logsig[(size_t)row * LSIG + i] * invw;
}

// ---------------- shared-memory layout ----------------
// double region first (8B aligned), fp32 weight region after.
#define D_H1D   0                     // 4096
#define D_W     (D_H1D + 4096)        // 2048
#define D_H1    (D_W + 2048)          // 256
#define D_H2    (D_H1 + 256)          // 256
#define D_G     (D_H2 + 256)          // 256
#define D_RED   (D_G + 256)           // 256
#define D_Y     (D_RED + 256)         // 128
#define D_YB    (D_Y + 128)           // 128
#define D_K1    (D_YB + 128)          // 128
#define D_TP    (D_K1 + 128)          // 128
#define D_B3    (D_TP + 128)          // 128
#define D_LS    (D_B3 + 128)          // 144 (137 used)
#define D_B1    (D_LS + 144)          // 16
#define D_B2    (D_B1 + 16)           // 16
#define D_D1    (D_B2 + 16)           // 16
#define D_D2    (D_D1 + 16)           // 16
#define D_A     (D_D2 + 16)           // 16
#define NDBL    (D_A + 16)            // 8032 doubles = 64256 B

#define F_W3T   0                     // 128 x 260
#define F_W2T   (F_W3T + 128 * 260)   // 16 x 260
#define F_W1T   (F_W2T + 16 * 260)    // 16 x 132
#define NFLT    (F_W1T + 16 * 132)    // 39552 floats = 158208 B

#define SMEM_BYTES (NDBL * 8 + NFLT * 4)   // 222464 B

__global__ void __launch_bounds__(TPB, 1)
cde_kernel(const float* __restrict__ ts,
           const float* __restrict__ x0,
           const float* __restrict__ c20a, const float* __restrict__ c20b,   // {l1_w, b3}
           const float* __restrict__ l1_b,
           const float* __restrict__ w1,
           const float* __restrict__ c25a, const float* __restrict__ c25b,   // {b1, b2}
           const float* __restrict__ w2,
           const float* __restrict__ w3,
           const float* __restrict__ l2_w, const float* __restrict__ l2_b,
           float* __restrict__ out) {
    extern __shared__ double smd[];
    double* sh1d = smd + D_H1D;
    double* sW   = smd + D_W;
    double* sh1  = smd + D_H1;
    double* sh2  = smd + D_H2;
    double* sg   = smd + D_G;
    double* sred = smd + D_RED;
    double* sy   = smd + D_Y;
    double* syb  = smd + D_YB;
    double* sk1  = smd + D_K1;
    double* stp  = smd + D_TP;
    double* sb3  = smd + D_B3;
    double* sls  = smd + D_LS;
    double* sb1  = smd + D_B1;
    double* sb2  = smd + D_B2;
    double* sd1  = smd + D_D1;
    double* sd2  = smd + D_D2;
    double* sA   = smd + D_A;
    float*  smf  = (float*)(smd + NDBL);
    float*  sw3t = smf + F_W3T;
    float*  sw2t = smf + F_W2T;
    float*  sw1t = smf + F_W1T;

    const int tid = threadIdx.x;
    const int cta = blockIdx.x;

    // ---- resolve ambiguous inputs (selectors written by prep_kernel) ----
    const int selA = g_sel2048;
    const int selB = g_sel256;
    const float* l1_w = (selA == 0) ? c20a : c20b;
    const float* b3   = (selA == 0) ? c20b : c20a;
    const float* b1   = (selB == 0) ? c25a : c25b;
    const float* b2   = (selB == 0) ? c25b : c25a;

    // ---- one-time: stage weight slices into SMEM (transposed, padded, fp32) ----
    for (int i = tid; i < 128 * 256; i += TPB) {     // w3 block
        int k = i >> 7, h = i & 127;
        sw3t[h * 260 + k] = w3[k * 2048 + cta * 128 + h];
    }
    for (int i = tid; i < 16 * 256; i += TPB) {
        int k = i >> 4, jj = i & 15;
        sw2t[jj * 260 + k] = w2[k * 256 + cta * 16 + jj];
    }
    for (int i = tid; i < 16 * 128; i += TPB) {
        int k = i >> 4, jj = i & 15;
        sw1t[jj * 132 + k] = w1[k * 256 + cta * 16 + jj];
    }
    if (tid < 16) {
        sb1[tid] = (double)b1[cta * 16 + tid];
        sb2[tid] = (double)b2[cta * 16 + tid];
    }
    if (tid < 128) {
        sb3[tid] = (double)b3[cta * 128 + tid];
        double a = (double)l1_b[tid];                // y0 = x0 @ l1_w + l1_b
        #pragma unroll
        for (int k = 0; k < 16; k++) a += (double)x0[k] * (double)l1_w[k * 128 + tid];
        sy[tid] = a; syb[tid] = a;
    }
    const float  dtf = (ts[T_N - 1] - ts[0]) / (float)NSTEPS;
    const double dt  = (double)dtf;
    __syncthreads();

    unsigned ep = 0;

    for (int ev = 0; ev < NEVAL; ev++) {
        // stage this eval's scaled log-signature row
        for (int i = tid; i < LSIG; i += TPB) sls[i] = g_lsbuf[ev * LSIG + i];

        // ---- P1: z1 slice = y @ w1[:,slice] + b1, silu ----
        {
            int jj = tid >> 4, kp = tid & 15;
            const float*  wv = &sw1t[jj * 132 + kp * 8];
            const double* yv = &sy[kp * 8];
            double a = 0.0;
            #pragma unroll
            for (int m = 0; m < 8; m++) a += (double)wv[m] * yv[m];
            sred[tid] = a;
        }
        __syncthreads();
        if (tid < 16) {
            double z = sb1[tid];
            #pragma unroll
            for (int q = 0; q < 16; q++) z += sred[tid * 16 + q];
            double s = 1.0 / (1.0 + exp(-z));
            double h = z * s;
            sd1[tid] = s + h * (1.0 - s);            // silu'(z)
            g_h1[cta * 16 + tid] = h;
        }
        grid_bar(++ep, tid, cta);

        // ---- P2: z2 slice = h1 @ w2[:,slice] + b2, silu ----
        sh1[tid] = ldcg_d(&g_h1[tid]);
        __syncthreads();
        {
            int jj = tid >> 4, kp = tid & 15;
            const float*  wv = &sw2t[jj * 260 + kp * 16];
            const double* hv = &sh1[kp * 16];
            double a = 0.0;
            #pragma unroll
            for (int m = 0; m < 16; m++) a += (double)wv[m] * hv[m];
            sred[tid] = a;
        }
        __syncthreads();
        if (tid < 16) {
            double z = sb2[tid];
            #pragma unroll
            for (int q = 0; q < 16; q++) z += sred[tid * 16 + q];
            double s = 1.0 / (1.0 + exp(-z));
            double h = z * s;
            sd2[tid] = s + h * (1.0 - s);
            g_h2[cta * 16 + tid] = h;
        }
        grid_bar(++ep, tid, cta);

        // ---- P3: z3 block = h2 @ w3_block + b3, W = tanh ----
        sh2[tid] = ldcg_d(&g_h2[tid]);
        __syncthreads();
        {
            int h = tid & 127, part = tid >> 7;
            const float*  wv = &sw3t[h * 260 + part * 128];
            const double* xv = &sh2[part * 128];
            double a = 0.0;
            #pragma unroll 16
            for (int m = 0; m < 128; m++) a += (double)wv[m] * xv[m];
            sred[tid] = a;
        }
        __syncthreads();
        if (tid < 128) {
            double z = sred[tid] + sred[tid + 128] + sb3[tid];
            double W = tanh(z);
            stp[tid] = 1.0 - W * W;                  // tanh'(z3)
            g_W[cta * 128 + tid] = W;
        }
        grid_bar(++ep, tid, cta);

        // ---- P4: tangent layer 1: h1d = silu'(z1) * (W_t @ w1[:,slice]) ----
        for (int i = tid; i < 2048; i += TPB) sW[i] = ldcg_d(&g_W[i]);
        __syncthreads();
        {
            int tg = tid >> 4, jj = tid & 15;
            const double* vv = &sW[tg * 128];
            const float*  wv = &sw1t[jj * 132];
            double a = 0.0;
            #pragma unroll 16
            for (int m = 0; m < 128; m++) a += vv[m] * (double)wv[m];
            g_h1d[tg * 256 + cta * 16 + jj] = sd1[jj] * a;
        }
        grid_bar(++ep, tid, cta);

        // ---- P5: tangent layer 2: h2d = silu'(z2) * (h1d @ w2[:,slice]) ----
        for (int i = tid; i < 4096; i += TPB) sh1d[i] = ldcg_d(&g_h1d[i]);
        __syncthreads();
        {
            int tg = tid >> 4, jj = tid & 15;
            const double* vv = &sh1d[tg * 256];
            const float*  wv = &sw2t[jj * 260];
            double a = 0.0;
            #pragma unroll 16
            for (int m = 0; m < 256; m++) a += vv[m] * (double)wv[m];
            g_h2d[tg * 256 + cta * 16 + jj] = sd2[jj] * a;
        }
        if (tid < 16) {                              // A[:, b] column from ls brackets
            double coef;
            if (tid == cta) coef = 0.0;
            else if (tid < cta) coef =  sls[17 + pair_index(tid, cta)];
            else                coef = -sls[17 + pair_index(cta, tid)];
            sA[tid] = coef;
        }
        grid_bar(++ep, tid, cta);

        // ---- P6: g = A^T h2d ; u = g @ w3_block ; partial res ----
        {
            double a = 0.0;
            #pragma unroll
            for (int tg = 0; tg < 16; tg++)
                a += sA[tg] * ldcg_d(&g_h2d[tg * 256 + tid]);
            sg[tid] = a;
        }
        __syncthreads();
        {
            int h = tid & 127, part = tid >> 7;
            const float*  wv = &sw3t[h * 260 + part * 128];
            const double* xv = &sg[part * 128];
            double a = 0.0;
            #pragma unroll 16
            for (int m = 0; m < 128; m++) a += (double)wv[m] * xv[m];
            sred[tid] = a;
        }
        __syncthreads();
        if (tid < 128) {
            double u = sred[tid] + sred[tid + 128];
            double W = sW[cta * 128 + tid];
            g_resP[cta * 128 + tid] = sls[1 + cta] * W + stp[tid] * u;
        }
        grid_bar(++ep, tid, cta);

        // ---- combine partials (fixed order) and Heun update (redundant per CTA) ----
        if (tid < 128) {
            double kv = 0.0;
            #pragma unroll
            for (int b = 0; b < 16; b++) kv += ldcg_d(&g_resP[b * 128 + tid]);
            if ((ev & 1) == 0) {
                sk1[tid] = kv;
                sy[tid] = syb[tid] + dt * kv;        // midpoint input for k2
            } else {
                double yn = syb[tid] + 0.5 * dt * (sk1[tid] + kv);
                syb[tid] = yn;
                sy[tid] = yn;
            }
        }
        __syncthreads();
    }

    // ---- classification head: softmax(y @ l2_w + l2_b), CTA 0 only ----
    if (cta == 0) {
        if (tid < 10) {
            double z = (double)l2_b[tid];
            for (int k = 0; k < 128; k++) z += syb[k] * (double)l2_w[k * 10 + tid];
            sred[tid] = z;
        }
        __syncthreads();
        if (tid == 0) {
            double mx = sred[0];
            for (int j = 1; j < 10; j++) mx = fmax(mx, sred[j]);
            double ex[10]; double ssum = 0.0;
            for (int j = 0; j < 10; j++) { ex[j] = exp(sred[j] - mx); ssum += ex[j]; }
            for (int j = 0; j < 10; j++) out[j] = (float)(ex[j] / ssum);
        }
    }
}

extern "C" void kernel_launch(void* const* d_in, const int* in_sizes, int n_in,
                              void* d_out, int out_size) {
    // ---- assumption-free input resolution by element count ----
    const float *ts = 0, *logsig = 0, *x0 = 0, *l1_b = 0, *w1 = 0, *w2 = 0,
                *w3 = 0, *l2_w = 0, *l2_b = 0;
    const float *c20[2] = {0, 0};   // 2048-sized candidates {l1_w, b3}
    const float *c25[2] = {0, 0};   // 256-sized candidates  {b1, b2}
    int n20 = 0, n25 = 0;
    for (int i = 0; i < n_in; i++) {
        const float* p = (const float*)d_in[i];
        switch (in_sizes[i]) {
            case T_N:      if (!ts) ts = p; break;           // ts / intervals (identical)
            case 27400000: logsig = p; break;
            case 16:       x0 = p; break;
            case 32768:    w1 = p; break;
            case 65536:    w2 = p; break;
            case 524288:   w3 = p; break;
            case 128:      l1_b = p; break;
            case 1280:     l2_w = p; break;
            case 10:       l2_b = p; break;
            case 2048:     if (n20 < 2) c20[n20++] = p; break;
            case 256:      if (n25 < 2) c25[n25++] = p; break;
            default: break;
        }
    }
    if (n20 == 1) c20[1] = c20[0];
    if (n25 == 1) c25[1] = c25[0];
    float* out = (float*)d_out;

    cudaFuncSetAttribute(cde_kernel, cudaFuncAttributeMaxDynamicSharedMemorySize,
                         SMEM_BYTES);

    prep_kernel<<<NEVAL + 2, 256>>>(ts, logsig, c20[0], c20[1], c25[0], c25[1]);
    cde_kernel<<<G, TPB, SMEM_BYTES>>>(ts, x0, c20[0], c20[1], l1_b, w1,
                                       c25[0], c25[1], w2, w3, l2_w, l2_b, out);
}

// round 9
// speedup vs baseline: 3.1402x; 3.1402x over previous
#include <cuda_runtime.h>
#include <math.h>

// ---------------- static problem dims ----------------
#define T_N     200001
#define DD      16
#define HH      128
#define WIDW    256
#define LSIG    137
#define NSTEPS  100
#define NEVAL   200
#define G       64          // persistent CTAs: 32 w3-cols each, 4 CTAs per tangent block
#define TPB     256

// ---------------- device scratch (no allocs allowed) ----------------
__device__ double g_lsbuf[NEVAL * LSIG];    // per-eval logsig row, pre-scaled by 1/interval
__device__ double g_h1[WIDW];
__device__ double g_h2[WIDW];
__device__ double g_W[DD * HH];             // 2048: vf output (tangent directions)
__device__ double g_h1d[DD * WIDW];         // 4096
__device__ double g_h2d[DD * WIDW];         // 4096
__device__ double g_resP[DD * HH];          // flat d*128+hh partial field result
__device__ volatile unsigned g_flag[G * 8]; // epoch flags, padded 32B apart
__device__ int g_sel2048;                   // 0 => cand0 is l1_w, 1 => cand1 is l1_w
__device__ int g_sel256;                    // 0 => cand0 is b1,   1 => cand1 is b1

__device__ __forceinline__ int pair_index(int i, int j) {
    return i * (2 * DD - 1 - i) / 2 + (j - i - 1);
}

__device__ __forceinline__ double ldcg_d(const double* p) {
    return __longlong_as_double(__ldcg((const long long*)p));
}

__device__ __forceinline__ void grid_bar(unsigned ep, int tid, int cta) {
    __threadfence();
    __syncthreads();
    if (tid == 0) g_flag[cta * 8] = ep;
    if (tid < G) {
        while (g_flag[tid * 8] < ep) { }
        __threadfence();
    }
    __syncthreads();
}

__device__ float block_maxabs(const float* p, int n) {
    __shared__ float red[256];
    float m = 0.f;
    for (int i = threadIdx.x; i < n; i += blockDim.x) m = fmaxf(m, fabsf(p[i]));
    red[threadIdx.x] = m;
    __syncthreads();
    for (int s = 128; s > 0; s >>= 1) {
        if (threadIdx.x < s) red[threadIdx.x] = fmaxf(red[threadIdx.x], red[threadIdx.x + s]);
        __syncthreads();
    }
    return red[0];
}

// ---------------- prep: per-eval t (exact fp32 accumulation), searchsorted idx,
//                  gather logsig row pre-scaled by 1/width in DOUBLE ----------------
__global__ void prep_kernel(const float* __restrict__ ts,
                            const float* __restrict__ logsig,
                            const float* __restrict__ c20a, const float* __restrict__ c20b,
                            const float* __restrict__ c25a, const float* __restrict__ c25b) {
    int e = blockIdx.x;

    if (e == NEVAL) {
        float m0 = block_maxabs(c20a, 2048);      // l1_w bound 0.25 vs b3 bound 0.0625
        if (threadIdx.x == 0) g_sel2048 = (m0 > 0.07f) ? 0 : 1;
        return;
    }
    if (e == NEVAL + 1) {
        float m0 = block_maxabs(c25a, 256);       // b1 bound 0.0884 vs b2 bound 0.0625
        if (threadIdx.x == 0) g_sel256 = (m0 > 0.0649f) ? 0 : 1;
        return;
    }

    __shared__ int    s_row;
    __shared__ double s_invw;
    if (threadIdx.x == 0) {
        if (e == 0) {
            for (int i = 0; i < G * 8; i++) g_flag[i] = 0u;
        }
        float ts0 = ts[0];
        float dt = (ts[T_N - 1] - ts0) / (float)NSTEPS;
        int s = e >> 1;
        float t = ts0;
        for (int i = 0; i < s; i++) t += dt;     // exact fp32 carry accumulation
        if (e & 1) t += dt;                       // k2 evaluated at t + dt

        int c = (int)(t * (float)(T_N - 1));
        int lo = c - 64; if (lo < 0) lo = 0;
        int hi = c + 64; if (hi > T_N - 2) hi = T_N - 2;
        int found = -1;
        if (lo == 0 || ts[lo] < t) {
            for (int j = lo; j <= hi; j++) {
                if (ts[j + 1] >= t) { found = j; break; }
            }
            if (found < 0 && hi == T_N - 2) found = T_N - 1;
        }
        if (found < 0) {
            int a = 0, b = T_N - 2, res = T_N - 1;
            while (a <= b) {
                int m = (a + b) >> 1;
                if (ts[m + 1] >= t) { res = m; b = m - 1; } else a = m + 1;
            }
            found = res;
        }
        int idx = found + 1;
        if (idx > T_N - 1) idx = T_N - 1;
        s_row  = idx - 1;
        s_invw = 1.0 / ((double)ts[idx] - (double)ts[idx - 1]);
    }
    __syncthreads();
    int row = s_row; double invw = s_invw;
    for (int i = threadIdx.x; i < LSIG; i += blockDim.x)
        g_lsbuf[e * LSIG + i] = (double)logsig[(size_t)row * LSIG + i] * invw;
}

// ---------------- shared-memory layout (doubles, odd strides => <=2-way LDS.64) ----
#define D_W3   0                        // 32 x 257
#define D_H1D  (D_W3 + 32 * 257)        // 16 x 257
#define D_SW   (D_H1D + 16 * 257)       // 16 x 130
#define D_W2   (D_SW + 16 * 130)        // 4 x 257
#define D_W1   (D_W2 + 4 * 257)         // 4 x 129
#define D_H1   (D_W1 + 4 * 129)         // 256
#define D_H2   (D_H1 + 256)             // 256
#define D_G    (D_H2 + 256)             // 256
#define D_RED  (D_G + 256)              // 256
#define D_Y    (D_RED + 256)            // 128
#define D_YB   (D_Y + 128)              // 128
#define D_K1   (D_YB + 128)             // 128
#define D_TP   (D_K1 + 128)             // 32
#define D_B3   (D_TP + 32)              // 32
#define D_LS   (D_B3 + 32)              // 144 (137 used)
#define D_B1   (D_LS + 144)             // 4
#define D_B2   (D_B1 + 4)               // 4
#define D_D1   (D_B2 + 4)               // 4
#define D_D2   (D_D1 + 4)               // 4
#define D_A    (D_D2 + 4)               // 16
#define NDBL   (D_A + 16)
#define SMEM_BYTES (NDBL * 8)

__global__ void __launch_bounds__(TPB, 1)
cde_kernel(const float* __restrict__ ts,
           const float* __restrict__ x0,
           const float* __restrict__ c20a, const float* __restrict__ c20b,   // {l1_w, b3}
           const float* __restrict__ l1_b,
           const float* __restrict__ w1,
           const float* __restrict__ c25a, const float* __restrict__ c25b,   // {b1, b2}
           const float* __restrict__ w2,
           const float* __restrict__ w3,
           const float* __restrict__ l2_w, const float* __restrict__ l2_b,
           float* __restrict__ out) {
    extern __shared__ double smd[];
    double* w3d  = smd + D_W3;    // [h<32][k<256] stride 257
    double* sh1d = smd + D_H1D;   // [tg<16][k<256] stride 257
    double* sW   = smd + D_SW;    // [tg<16][m<128] stride 130
    double* w2d  = smd + D_W2;    // [jj<4][k<256] stride 257
    double* w1d  = smd + D_W1;    // [jj<4][k<128] stride 129
    double* sh1  = smd + D_H1;
    double* sh2  = smd + D_H2;
    double* sg   = smd + D_G;
    double* sred = smd + D_RED;
    double* sy   = smd + D_Y;
    double* syb  = smd + D_YB;
    double* sk1  = smd + D_K1;
    double* stp  = smd + D_TP;
    double* sb3  = smd + D_B3;
    double* sls  = smd + D_LS;
    double* sb1  = smd + D_B1;
    double* sb2  = smd + D_B2;
    double* sd1  = smd + D_D1;
    double* sd2  = smd + D_D2;
    double* sA   = smd + D_A;

    const int tid = threadIdx.x;
    const int cta = blockIdx.x;
    const int dblk = cta >> 2;          // tangent/output block this CTA feeds (0..15)
    const int hbase = (cta & 3) * 32;   // h-offset within the 128-wide block

    // ---- resolve ambiguous inputs (selectors written by prep_kernel) ----
    const int selA = g_sel2048;
    const int selB = g_sel256;
    const float* l1_w = (selA == 0) ? c20a : c20b;
    const float* b3   = (selA == 0) ? c20b : c20a;
    const float* b1   = (selB == 0) ? c25a : c25b;
    const float* b2   = (selB == 0) ? c25b : c25a;

    // ---- one-time: stage weight slices as DOUBLE in SMEM ----
    for (int i = tid; i < 32 * 256; i += TPB) {      // w3 cols [cta*32, cta*32+32)
        int h = i & 31, k = i >> 5;
        w3d[h * 257 + k] = (double)w3[k * 2048 + cta * 32 + h];
    }
    for (int i = tid; i < 4 * 256; i += TPB) {       // w2 cols [cta*4, cta*4+4)
        int jj = i & 3, k = i >> 2;
        w2d[jj * 257 + k] = (double)w2[k * 256 + cta * 4 + jj];
    }
    for (int i = tid; i < 4 * 128; i += TPB) {       // w1 cols [cta*4, cta*4+4)
        int jj = i & 3, k = i >> 2;
        w1d[jj * 129 + k] = (double)w1[k * 256 + cta * 4 + jj];
    }
    if (tid < 4) {
        sb1[tid] = (double)b1[cta * 4 + tid];
        sb2[tid] = (double)b2[cta * 4 + tid];
    }
    if (tid < 32) sb3[tid] = (double)b3[cta * 32 + tid];
    if (tid < 128) {
        double a = (double)l1_b[tid];                // y0 = x0 @ l1_w + l1_b
        #pragma unroll
        for (int k = 0; k < 16; k++) a += (double)x0[k] * (double)l1_w[k * 128 + tid];
        sy[tid] = a; syb[tid] = a;
    }
    const double dt = (double)((ts[T_N - 1] - ts[0]) / (float)NSTEPS);
    __syncthreads();

    unsigned ep = 0;
    const int lane = tid & 31;

    for (int ev = 0; ev < NEVAL; ev++) {
        // stage this eval's scaled log-signature row
        for (int i = tid; i < LSIG; i += TPB) sls[i] = g_lsbuf[ev * LSIG + i];

        // ---- P1: z1[jj] = y . w1[:,cta*4+jj] + b1 ; silu ----
        if (tid < 128) {
            int jj = tid >> 5;
            double a0 = 0.0, a1 = 0.0, a2 = 0.0, a3 = 0.0;
            a0 += w1d[jj * 129 + lane      ] * sy[lane      ];
            a1 += w1d[jj * 129 + lane + 32 ] * sy[lane + 32 ];
            a2 += w1d[jj * 129 + lane + 64 ] * sy[lane + 64 ];
            a3 += w1d[jj * 129 + lane + 96 ] * sy[lane + 96 ];
            double a = (a0 + a1) + (a2 + a3);
            #pragma unroll
            for (int o = 16; o > 0; o >>= 1) a += __shfl_xor_sync(0xffffffffu, a, o);
            if (lane == 0) {
                double z = a + sb1[jj];
                double s = 1.0 / (1.0 + exp(-z));
                double h = z * s;
                sd1[jj] = s + h * (1.0 - s);
                g_h1[cta * 4 + jj] = h;
            }
        }
        grid_bar(++ep, tid, cta);

        // ---- P2: z2[jj] = h1 . w2[:,cta*4+jj] + b2 ; silu ----
        sh1[tid] = ldcg_d(&g_h1[tid]);
        __syncthreads();
        if (tid < 128) {
            int jj = tid >> 5;
            double a0 = 0.0, a1 = 0.0, a2 = 0.0, a3 = 0.0;
            #pragma unroll
            for (int m = 0; m < 8; m += 4) {
                a0 += w2d[jj * 257 + lane + 32 * (m + 0)] * sh1[lane + 32 * (m + 0)];
                a1 += w2d[jj * 257 + lane + 32 * (m + 1)] * sh1[lane + 32 * (m + 1)];
                a2 += w2d[jj * 257 + lane + 32 * (m + 2)] * sh1[lane + 32 * (m + 2)];
                a3 += w2d[jj * 257 + lane + 32 * (m + 3)] * sh1[lane + 32 * (m + 3)];
            }
            double a = (a0 + a1) + (a2 + a3);
            #pragma unroll
            for (int o = 16; o > 0; o >>= 1) a += __shfl_xor_sync(0xffffffffu, a, o);
            if (lane == 0) {
                double z = a + sb2[jj];
                double s = 1.0 / (1.0 + exp(-z));
                double h = z * s;
                sd2[jj] = s + h * (1.0 - s);
                g_h2[cta * 4 + jj] = h;
            }
        }
        grid_bar(++ep, tid, cta);

        // ---- P3: z3[h] = h2 . w3[:,cta*32+h] + b3 ; W = tanh ----
        sh2[tid] = ldcg_d(&g_h2[tid]);
        __syncthreads();
        {
            int h = tid & 31, part = tid >> 5;       // 8 parts, k = part + 8*m
            double a0 = 0.0, a1 = 0.0, a2 = 0.0, a3 = 0.0;
            #pragma unroll
            for (int m = 0; m < 32; m += 4) {
                a0 += w3d[h * 257 + part + 8 * (m + 0)] * sh2[part + 8 * (m + 0)];
                a1 += w3d[h * 257 + part + 8 * (m + 1)] * sh2[part + 8 * (m + 1)];
                a2 += w3d[h * 257 + part + 8 * (m + 2)] * sh2[part + 8 * (m + 2)];
                a3 += w3d[h * 257 + part + 8 * (m + 3)] * sh2[part + 8 * (m + 3)];
            }
            sred[part * 32 + h] = (a0 + a1) + (a2 + a3);
        }
        __syncthreads();
        if (tid < 32) {
            double z = sb3[tid];
            #pragma unroll
            for (int p = 0; p < 8; p++) z += sred[p * 32 + tid];
            double W = tanh(z);
            stp[tid] = 1.0 - W * W;
            g_W[cta * 32 + tid] = W;
        }
        grid_bar(++ep, tid, cta);

        // ---- P4: h1d[tg][jj] = silu'(z1[jj]) * (W[tg,:] . w1[:,jj-col]) ----
        for (int i = tid; i < 2048; i += TPB)
            sW[(i >> 7) * 130 + (i & 127)] = ldcg_d(&g_W[i]);
        __syncthreads();
        {
            int outp = tid >> 2, q = tid & 3;        // 64 outputs x 4 threads
            int tg = outp >> 2, jj = outp & 3;       // k = q + 4*m
            double a0 = 0.0, a1 = 0.0, a2 = 0.0, a3 = 0.0;
            #pragma unroll
            for (int m = 0; m < 32; m += 4) {
                a0 += sW[tg * 130 + q + 4 * (m + 0)] * w1d[jj * 129 + q + 4 * (m + 0)];
                a1 += sW[tg * 130 + q + 4 * (m + 1)] * w1d[jj * 129 + q + 4 * (m + 1)];
                a2 += sW[tg * 130 + q + 4 * (m + 2)] * w1d[jj * 129 + q + 4 * (m + 2)];
                a3 += sW[tg * 130 + q + 4 * (m + 3)] * w1d[jj * 129 + q + 4 * (m + 3)];
            }
            double a = (a0 + a1) + (a2 + a3);
            a += __shfl_xor_sync(0xffffffffu, a, 1);
            a += __shfl_xor_sync(0xffffffffu, a, 2);
            if (q == 0) g_h1d[tg * 256 + cta * 4 + jj] = sd1[jj] * a;
        }
        grid_bar(++ep, tid, cta);

        // ---- P5: h2d[tg][jj] = silu'(z2[jj]) * (h1d[tg,:] . w2[:,jj-col]) ----
        for (int i = tid; i < 4096; i += TPB)
            sh1d[(i >> 8) * 257 + (i & 255)] = ldcg_d(&g_h1d[i]);
        __syncthreads();
        {
            int outp = tid >> 2, q = tid & 3;
            int tg = outp >> 2, jj = outp & 3;       // k = q + 4*m, m<64
            double a0 = 0.0, a1 = 0.0, a2 = 0.0, a3 = 0.0;
            #pragma unroll
            for (int m = 0; m < 64; m += 4) {
                a0 += sh1d[tg * 257 + q + 4 * (m + 0)] * w2d[jj * 257 + q + 4 * (m + 0)];
                a1 += sh1d[tg * 257 + q + 4 * (m + 1)] * w2d[jj * 257 + q + 4 * (m + 1)];
                a2 += sh1d[tg * 257 + q + 4 * (m + 2)] * w2d[jj * 257 + q + 4 * (m + 2)];
                a3 += sh1d[tg * 257 + q + 4 * (m + 3)] * w2d[jj * 257 + q + 4 * (m + 3)];
            }
            double a = (a0 + a1) + (a2 + a3);
            a += __shfl_xor_sync(0xffffffffu, a, 1);
            a += __shfl_xor_sync(0xffffffffu, a, 2);
            if (q == 0) g_h2d[tg * 256 + cta * 4 + jj] = sd2[jj] * a;
        }
        if (tid < 16) {                              // A[:, dblk] bracket coefficients
            double coef;
            if (tid == dblk) coef = 0.0;
            else if (tid < dblk) coef =  sls[17 + pair_index(tid, dblk)];
            else                 coef = -sls[17 + pair_index(dblk, tid)];
            sA[tid] = coef;
        }
        grid_bar(++ep, tid, cta);

        // ---- P6: g = A^T h2d ; u[h] = g . w3[:,col] ; partial res ----
        {
            double a0 = 0.0, a1 = 0.0, a2 = 0.0, a3 = 0.0;
            #pragma unroll
            for (int tg = 0; tg < 16; tg += 4) {
                a0 += sA[tg + 0] * ldcg_d(&g_h2d[(tg + 0) * 256 + tid]);
                a1 += sA[tg + 1] * ldcg_d(&g_h2d[(tg + 1) * 256 + tid]);
                a2 += sA[tg + 2] * ldcg_d(&g_h2d[(tg + 2) * 256 + tid]);
                a3 += sA[tg + 3] * ldcg_d(&g_h2d[(tg + 3) * 256 + tid]);
            }
            sg[tid] = (a0 + a1) + (a2 + a3);
        }
        __syncthreads();
        {
            int h = tid & 31, part = tid >> 5;
            double a0 = 0.0, a1 = 0.0, a2 = 0.0, a3 = 0.0;
            #pragma unroll
            for (int m = 0; m < 32; m += 4) {
                a0 += w3d[h * 257 + part + 8 * (m + 0)] * sg[part + 8 * (m + 0)];
                a1 += w3d[h * 257 + part + 8 * (m + 1)] * sg[part + 8 * (m + 1)];
                a2 += w3d[h * 257 + part + 8 * (m + 2)] * sg[part + 8 * (m + 2)];
                a3 += w3d[h * 257 + part + 8 * (m + 3)] * sg[part + 8 * (m + 3)];
            }
            sred[part * 32 + h] = (a0 + a1) + (a2 + a3);
        }
        __syncthreads();
        if (tid < 32) {
            double u = 0.0;
            #pragma unroll
            for (int p = 0; p < 8; p++) u += sred[p * 32 + tid];
            double W = sW[dblk * 130 + hbase + tid];
            g_resP[cta * 32 + tid] = sls[1 + dblk] * W + stp[tid] * u;
        }
        grid_bar(++ep, tid, cta);

        // ---- combine partials (fixed order) and Heun update (redundant per CTA) ----
        if (tid < 128) {
            double k0 = 0.0, k1v = 0.0, k2v = 0.0, k3v = 0.0;
            #pragma unroll
            for (int dd = 0; dd < 16; dd += 4) {
                k0  += ldcg_d(&g_resP[(dd + 0) * 128 + tid]);
                k1v += ldcg_d(&g_resP[(dd + 1) * 128 + tid]);
                k2v += ldcg_d(&g_resP[(dd + 2) * 128 + tid]);
                k3v += ldcg_d(&g_resP[(dd + 3) * 128 + tid]);
            }
            double kv = (k0 + k1v) + (k2v + k3v);
            if ((ev & 1) == 0) {
                sk1[tid] = kv;
                sy[tid] = syb[tid] + dt * kv;        // midpoint input for k2
            } else {
                double yn = syb[tid] + 0.5 * dt * (sk1[tid] + kv);
                syb[tid] = yn;
                sy[tid] = yn;
            }
        }
        __syncthreads();
    }

    // ---- classification head: softmax(y @ l2_w + l2_b), CTA 0 only ----
    if (cta == 0) {
        if (tid < 10) {
            double z = (double)l2_b[tid];
            for (int k = 0; k < 128; k++) z += syb[k] * (double)l2_w[k * 10 + tid];
            sred[tid] = z;
        }
        __syncthreads();
        if (tid == 0) {
            double mx = sred[0];
            for (int j = 1; j < 10; j++) mx = fmax(mx, sred[j]);
            double ex[10]; double ssum = 0.0;
            for (int j = 0; j < 10; j++) { ex[j] = exp(sred[j] - mx); ssum += ex[j]; }
            for (int j = 0; j < 10; j++) out[j] = (float)(ex[j] / ssum);
        }
    }
}

extern "C" void kernel_launch(void* const* d_in, const int* in_sizes, int n_in,
                              void* d_out, int out_size) {
    // ---- assumption-free input resolution by element count ----
    const float *ts = 0, *logsig = 0, *x0 = 0, *l1_b = 0, *w1 = 0, *w2 = 0,
                *w3 = 0, *l2_w = 0, *l2_b = 0;
    const float *c20[2] = {0, 0};   // 2048-sized candidates {l1_w, b3}
    const float *c25[2] = {0, 0};   // 256-sized candidates  {b1, b2}
    int n20 = 0, n25 = 0;
    for (int i = 0; i < n_in; i++) {
        const float* p = (const float*)d_in[i];
        switch (in_sizes[i]) {
            case T_N:      if (!ts) ts = p; break;           // ts / intervals (identical)
            case 27400000: logsig = p; break;
            case 16:       x0 = p; break;
            case 32768:    w1 = p; break;
            case 65536:    w2 = p; break;
            case 524288:   w3 = p; break;
            case 128:      l1_b = p; break;
            case 1280:     l2_w = p; break;
            case 10:       l2_b = p; break;
            case 2048:     if (n20 < 2) c20[n20++] = p; break;
            case 256:      if (n25 < 2) c25[n25++] = p; break;
            default: break;
        }
    }
    if (n20 == 1) c20[1] = c20[0];
    if (n25 == 1) c25[1] = c25[0];
    float* out = (float*)d_out;

    cudaFuncSetAttribute(cde_kernel, cudaFuncAttributeMaxDynamicSharedMemorySize,
                         SMEM_BYTES);

    prep_kernel<<<NEVAL + 2, 256>>>(ts, logsig, c20[0], c20[1], c25[0], c25[1]);
    cde_kernel<<<G, TPB, SMEM_BYTES>>>(ts, x0, c20[0], c20[1], l1_b, w1,
                                       c25[0], c25[1], w2, w3, l2_w, l2_b, out);
}

// round 10
// speedup vs baseline: 3.8295x; 1.2195x over previous
#include <cuda_runtime.h>
#include <math.h>

// ---------------- static problem dims ----------------
#define T_N     200001
#define DD      16
#define HH      128
#define WIDW    256
#define LSIG    137
#define NSTEPS  100
#define NEVAL   200
#define G       64          // persistent CTAs: 32 w3-cols each, 4 CTAs per tangent block
#define TPB     256

// ---------------- device scratch (no allocs allowed) ----------------
__device__ double g_lsbuf[NEVAL * LSIG];    // per-eval logsig row, pre-scaled by 1/interval
__device__ double g_h1[WIDW];
__device__ double g_h2[WIDW];
__device__ double g_W[DD * HH];             // 2048: vf output (tangent directions)
__device__ double g_h1d[DD * WIDW];         // 4096
__device__ double g_h2d[DD * WIDW];         // 4096
__device__ double g_resP[DD * HH];          // flat d*128+hh partial field result
__device__ unsigned g_cnt;                  // single-counter grid barrier (gpu scope)
__device__ int g_sel2048;                   // 0 => cand0 is l1_w, 1 => cand1 is l1_w
__device__ int g_sel256;                    // 0 => cand0 is b1,   1 => cand1 is b1

__device__ __forceinline__ int pair_index(int i, int j) {
    return i * (2 * DD - 1 - i) / 2 + (j - i - 1);
}

__device__ __forceinline__ double ldcg_d(const double* p) {
    return __longlong_as_double(__ldcg((const long long*)p));
}

__device__ __forceinline__ unsigned ld_acq_gpu(const unsigned* p) {
    unsigned v;
    asm volatile("ld.acquire.gpu.global.u32 %0, [%1];" : "=r"(v) : "l"(p) : "memory");
    return v;
}

// gpu-scope single-counter grid barrier: arrival via RED, wait via acquire poll.
__device__ __forceinline__ void grid_bar(unsigned ep, int tid) {
    __threadfence();                         // release own prior stores (gpu scope)
    __syncthreads();
    if (tid == 0) {
        atomicAdd(&g_cnt, 1u);               // gpu-scope RED, same-address (fast)
        while (ld_acq_gpu(&g_cnt) < ep * (unsigned)G) { }
    }
    __syncthreads();                         // cta-scope chain publishes acquire to all
}

__device__ float block_maxabs(const float* p, int n) {
    __shared__ float red[256];
    float m = 0.f;
    for (int i = threadIdx.x; i < n; i += blockDim.x) m = fmaxf(m, fabsf(p[i]));
    red[threadIdx.x] = m;
    __syncthreads();
    for (int s = 128; s > 0; s >>= 1) {
        if (threadIdx.x < s) red[threadIdx.x] = fmaxf(red[threadIdx.x], red[threadIdx.x + s]);
        __syncthreads();
    }
    return red[0];
}

// ---------------- prep: per-eval t (exact fp32 accumulation), searchsorted idx,
//                  gather logsig row pre-scaled by 1/width in DOUBLE ----------------
__global__ void prep_kernel(const float* __restrict__ ts,
                            const float* __restrict__ logsig,
                            const float* __restrict__ c20a, const float* __restrict__ c20b,
                            const float* __restrict__ c25a, const float* __restrict__ c25b) {
    int e = blockIdx.x;

    if (e == NEVAL) {
        float m0 = block_maxabs(c20a, 2048);      // l1_w bound 0.25 vs b3 bound 0.0625
        if (threadIdx.x == 0) g_sel2048 = (m0 > 0.07f) ? 0 : 1;
        return;
    }
    if (e == NEVAL + 1) {
        float m0 = block_maxabs(c25a, 256);       // b1 bound 0.0884 vs b2 bound 0.0625
        if (threadIdx.x == 0) g_sel256 = (m0 > 0.0649f) ? 0 : 1;
        return;
    }

    __shared__ int    s_row;
    __shared__ double s_invw;
    if (threadIdx.x == 0) {
        if (e == 0) g_cnt = 0u;                   // reset barrier counter each launch
        float ts0 = ts[0];
        float dt = (ts[T_N - 1] - ts0) / (float)NSTEPS;
        int s = e >> 1;
        float t = ts0;
        for (int i = 0; i < s; i++) t += dt;     // exact fp32 carry accumulation
        if (e & 1) t += dt;                       // k2 evaluated at t + dt

        int c = (int)(t * (float)(T_N - 1));
        int lo = c - 64; if (lo < 0) lo = 0;
        int hi = c + 64; if (hi > T_N - 2) hi = T_N - 2;
        int found = -1;
        if (lo == 0 || ts[lo] < t) {
            for (int j = lo; j <= hi; j++) {
                if (ts[j + 1] >= t) { found = j; break; }
            }
            if (found < 0 && hi == T_N - 2) found = T_N - 1;
        }
        if (found < 0) {
            int a = 0, b = T_N - 2, res = T_N - 1;
            while (a <= b) {
                int m = (a + b) >> 1;
                if (ts[m + 1] >= t) { res = m; b = m - 1; } else a = m + 1;
            }
            found = res;
        }
        int idx = found + 1;
        if (idx > T_N - 1) idx = T_N - 1;
        s_row  = idx - 1;
        s_invw = 1.0 / ((double)ts[idx] - (double)ts[idx - 1]);
    }
    __syncthreads();
    int row = s_row; double invw = s_invw;
    for (int i = threadIdx.x; i < LSIG; i += blockDim.x)
        g_lsbuf[e * LSIG + i] = (double)logsig[(size_t)row * LSIG + i] * invw;
}

// ---------------- shared-memory layout (doubles, odd strides => <=2-way LDS.64) ----
#define D_W3   0                        // 32 x 257
#define D_H1D  (D_W3 + 32 * 257)        // 16 x 257
#define D_SW   (D_H1D + 16 * 257)       // 16 x 130
#define D_W2   (D_SW + 16 * 130)        // 4 x 257
#define D_W1   (D_W2 + 4 * 257)         // 4 x 129
#define D_H1   (D_W1 + 4 * 129)         // 256
#define D_H2   (D_H1 + 256)             // 256
#define D_G    (D_H2 + 256)             // 256
#define D_RED  (D_G + 256)              // 256
#define D_Y    (D_RED + 256)            // 128
#define D_YB   (D_Y + 128)              // 128
#define D_K1   (D_YB + 128)             // 128
#define D_TP   (D_K1 + 128)             // 32
#define D_B3   (D_TP + 32)              // 32
#define D_LS   (D_B3 + 32)              // 144 (137 used)
#define D_B1   (D_LS + 144)             // 4
#define D_B2   (D_B1 + 4)               // 4
#define D_D1   (D_B2 + 4)               // 4
#define D_D2   (D_D1 + 4)               // 4
#define D_A    (D_D2 + 4)               // 16
#define NDBL   (D_A + 16)
#define SMEM_BYTES (NDBL * 8)

__global__ void __launch_bounds__(TPB, 1)
cde_kernel(const float* __restrict__ ts,
           const float* __restrict__ x0,
           const float* __restrict__ c20a, const float* __restrict__ c20b,   // {l1_w, b3}
           const float* __restrict__ l1_b,
           const float* __restrict__ w1,
           const float* __restrict__ c25a, const float* __restrict__ c25b,   // {b1, b2}
           const float* __restrict__ w2,
           const float* __restrict__ w3,
           const float* __restrict__ l2_w, const float* __restrict__ l2_b,
           float* __restrict__ out) {
    extern __shared__ double smd[];
    double* w3d  = smd + D_W3;    // [h<32][k<256] stride 257
    double* sh1d = smd + D_H1D;   // [tg<16][k<256] stride 257
    double* sW   = smd + D_SW;    // [tg<16][m<128] stride 130
    double* w2d  = smd + D_W2;    // [jj<4][k<256] stride 257
    double* w1d  = smd + D_W1;    // [jj<4][k<128] stride 129
    double* sh1  = smd + D_H1;
    double* sh2  = smd + D_H2;
    double* sg   = smd + D_G;
    double* sred = smd + D_RED;
    double* sy   = smd + D_Y;
    double* syb  = smd + D_YB;
    double* sk1  = smd + D_K1;
    double* stp  = smd + D_TP;
    double* sb3  = smd + D_B3;
    double* sls  = smd + D_LS;
    double* sb1  = smd + D_B1;
    double* sb2  = smd + D_B2;
    double* sd1  = smd + D_D1;
    double* sd2  = smd + D_D2;
    double* sA   = smd + D_A;

    const int tid = threadIdx.x;
    const int cta = blockIdx.x;
    const int dblk = cta >> 2;          // tangent/output block this CTA feeds (0..15)
    const int hbase = (cta & 3) * 32;   // h-offset within the 128-wide block

    // ---- resolve ambiguous inputs (selectors written by prep_kernel) ----
    const int selA = g_sel2048;
    const int selB = g_sel256;
    const float* l1_w = (selA == 0) ? c20a : c20b;
    const float* b3   = (selA == 0) ? c20b : c20a;
    const float* b1   = (selB == 0) ? c25a : c25b;
    const float* b2   = (selB == 0) ? c25b : c25a;

    // ---- one-time: stage weight slices as DOUBLE in SMEM ----
    for (int i = tid; i < 32 * 256; i += TPB) {      // w3 cols [cta*32, cta*32+32)
        int h = i & 31, k = i >> 5;
        w3d[h * 257 + k] = (double)w3[k * 2048 + cta * 32 + h];
    }
    for (int i = tid; i < 4 * 256; i += TPB) {       // w2 cols [cta*4, cta*4+4)
        int jj = i & 3, k = i >> 2;
        w2d[jj * 257 + k] = (double)w2[k * 256 + cta * 4 + jj];
    }
    for (int i = tid; i < 4 * 128; i += TPB) {       // w1 cols [cta*4, cta*4+4)
        int jj = i & 3, k = i >> 2;
        w1d[jj * 129 + k] = (double)w1[k * 256 + cta * 4 + jj];
    }
    if (tid < 4) {
        sb1[tid] = (double)b1[cta * 4 + tid];
        sb2[tid] = (double)b2[cta * 4 + tid];
    }
    if (tid < 32) sb3[tid] = (double)b3[cta * 32 + tid];
    if (tid < 128) {
        double a = (double)l1_b[tid];                // y0 = x0 @ l1_w + l1_b
        #pragma unroll
        for (int k = 0; k < 16; k++) a += (double)x0[k] * (double)l1_w[k * 128 + tid];
        sy[tid] = a; syb[tid] = a;
    }
    const double dt = (double)((ts[T_N - 1] - ts[0]) / (float)NSTEPS);
    __syncthreads();

    unsigned ep = 0;
    const int lane = tid & 31;

    for (int ev = 0; ev < NEVAL; ev++) {
        // stage this eval's scaled log-signature row
        for (int i = tid; i < LSIG; i += TPB) sls[i] = g_lsbuf[ev * LSIG + i];

        // ---- P1: z1[jj] = y . w1[:,cta*4+jj] + b1 ; silu ----
        if (tid < 128) {
            int jj = tid >> 5;
            double a0 = 0.0, a1 = 0.0, a2 = 0.0, a3 = 0.0;
            a0 += w1d[jj * 129 + lane      ] * sy[lane      ];
            a1 += w1d[jj * 129 + lane + 32 ] * sy[lane + 32 ];
            a2 += w1d[jj * 129 + lane + 64 ] * sy[lane + 64 ];
            a3 += w1d[jj * 129 + lane + 96 ] * sy[lane + 96 ];
            double a = (a0 + a1) + (a2 + a3);
            #pragma unroll
            for (int o = 16; o > 0; o >>= 1) a += __shfl_xor_sync(0xffffffffu, a, o);
            if (lane == 0) {
                double z = a + sb1[jj];
                double s = 1.0 / (1.0 + exp(-z));
                double h = z * s;
                sd1[jj] = s + h * (1.0 - s);
                g_h1[cta * 4 + jj] = h;
            }
        }
        grid_bar(++ep, tid);

        // ---- P2: z2[jj] = h1 . w2[:,cta*4+jj] + b2 ; silu ----
        sh1[tid] = ldcg_d(&g_h1[tid]);
        __syncthreads();
        if (tid < 128) {
            int jj = tid >> 5;
            double a0 = 0.0, a1 = 0.0, a2 = 0.0, a3 = 0.0;
            #pragma unroll
            for (int m = 0; m < 8; m += 4) {
                a0 += w2d[jj * 257 + lane + 32 * (m + 0)] * sh1[lane + 32 * (m + 0)];
                a1 += w2d[jj * 257 + lane + 32 * (m + 1)] * sh1[lane + 32 * (m + 1)];
                a2 += w2d[jj * 257 + lane + 32 * (m + 2)] * sh1[lane + 32 * (m + 2)];
                a3 += w2d[jj * 257 + lane + 32 * (m + 3)] * sh1[lane + 32 * (m + 3)];
            }
            double a = (a0 + a1) + (a2 + a3);
            #pragma unroll
            for (int o = 16; o > 0; o >>= 1) a += __shfl_xor_sync(0xffffffffu, a, o);
            if (lane == 0) {
                double z = a + sb2[jj];
                double s = 1.0 / (1.0 + exp(-z));
                double h = z * s;
                sd2[jj] = s + h * (1.0 - s);
                g_h2[cta * 4 + jj] = h;
            }
        }
        grid_bar(++ep, tid);

        // ---- P3: z3[h] = h2 . w3[:,cta*32+h] + b3 ; W = tanh ----
        sh2[tid] = ldcg_d(&g_h2[tid]);
        __syncthreads();
        {
            int h = tid & 31, part = tid >> 5;       // 8 parts, k = part + 8*m
            double a0 = 0.0, a1 = 0.0, a2 = 0.0, a3 = 0.0;
            #pragma unroll
            for (int m = 0; m < 32; m += 4) {
                a0 += w3d[h * 257 + part + 8 * (m + 0)] * sh2[part + 8 * (m + 0)];
                a1 += w3d[h * 257 + part + 8 * (m + 1)] * sh2[part + 8 * (m + 1)];
                a2 += w3d[h * 257 + part + 8 * (m + 2)] * sh2[part + 8 * (m + 2)];
                a3 += w3d[h * 257 + part + 8 * (m + 3)] * sh2[part + 8 * (m + 3)];
            }
            sred[part * 32 + h] = (a0 + a1) + (a2 + a3);
        }
        __syncthreads();
        if (tid < 32) {
            double z = sb3[tid];
            #pragma unroll
            for (int p = 0; p < 8; p++) z += sred[p * 32 + tid];
            double W = tanh(z);
            stp[tid] = 1.0 - W * W;
            g_W[cta * 32 + tid] = W;
        }
        grid_bar(++ep, tid);

        // ---- P4: h1d[tg][jj] = silu'(z1[jj]) * (W[tg,:] . w1[:,jj-col]) ----
        for (int i = tid; i < 2048; i += TPB)
            sW[(i >> 7) * 130 + (i & 127)] = ldcg_d(&g_W[i]);
        __syncthreads();
        {
            int outp = tid >> 2, q = tid & 3;        // 64 outputs x 4 threads
            int tg = outp >> 2, jj = outp & 3;       // k = q + 4*m
            double a0 = 0.0, a1 = 0.0, a2 = 0.0, a3 = 0.0;
            #pragma unroll
            for (int m = 0; m < 32; m += 4) {
                a0 += sW[tg * 130 + q + 4 * (m + 0)] * w1d[jj * 129 + q + 4 * (m + 0)];
                a1 += sW[tg * 130 + q + 4 * (m + 1)] * w1d[jj * 129 + q + 4 * (m + 1)];
                a2 += sW[tg * 130 + q + 4 * (m + 2)] * w1d[jj * 129 + q + 4 * (m + 2)];
                a3 += sW[tg * 130 + q + 4 * (m + 3)] * w1d[jj * 129 + q + 4 * (m + 3)];
            }
            double a = (a0 + a1) + (a2 + a3);
            a += __shfl_xor_sync(0xffffffffu, a, 1);
            a += __shfl_xor_sync(0xffffffffu, a, 2);
            if (q == 0) g_h1d[tg * 256 + cta * 4 + jj] = sd1[jj] * a;
        }
        grid_bar(++ep, tid);

        // ---- P5: h2d[tg][jj] = silu'(z2[jj]) * (h1d[tg,:] . w2[:,jj-col]) ----
        for (int i = tid; i < 4096; i += TPB)
            sh1d[(i >> 8) * 257 + (i & 255)] = ldcg_d(&g_h1d[i]);
        __syncthreads();
        {
            int outp = tid >> 2, q = tid & 3;
            int tg = outp >> 2, jj = outp & 3;       // k = q + 4*m, m<64
            double a0 = 0.0, a1 = 0.0, a2 = 0.0, a3 = 0.0;
            #pragma unroll
            for (int m = 0; m < 64; m += 4) {
                a0 += sh1d[tg * 257 + q + 4 * (m + 0)] * w2d[jj * 257 + q + 4 * (m + 0)];
                a1 += sh1d[tg * 257 + q + 4 * (m + 1)] * w2d[jj * 257 + q + 4 * (m + 1)];
                a2 += sh1d[tg * 257 + q + 4 * (m + 2)] * w2d[jj * 257 + q + 4 * (m + 2)];
                a3 += sh1d[tg * 257 + q + 4 * (m + 3)] * w2d[jj * 257 + q + 4 * (m + 3)];
            }
            double a = (a0 + a1) + (a2 + a3);
            a += __shfl_xor_sync(0xffffffffu, a, 1);
            a += __shfl_xor_sync(0xffffffffu, a, 2);
            if (q == 0) g_h2d[tg * 256 + cta * 4 + jj] = sd2[jj] * a;
        }
        if (tid < 16) {                              // A[:, dblk] bracket coefficients
            double coef;
            if (tid == dblk) coef = 0.0;
            else if (tid < dblk) coef =  sls[17 + pair_index(tid, dblk)];
            else                 coef = -sls[17 + pair_index(dblk, tid)];
            sA[tid] = coef;
        }
        grid_bar(++ep, tid);

        // ---- P6: g = A^T h2d ; u[h] = g . w3[:,col] ; partial res ----
        {
            double a0 = 0.0, a1 = 0.0, a2 = 0.0, a3 = 0.0;
            #pragma unroll
            for (int tg = 0; tg < 16; tg += 4) {
                a0 += sA[tg + 0] * ldcg_d(&g_h2d[(tg + 0) * 256 + tid]);
                a1 += sA[tg + 1] * ldcg_d(&g_h2d[(tg + 1) * 256 + tid]);
                a2 += sA[tg + 2] * ldcg_d(&g_h2d[(tg + 2) * 256 + tid]);
                a3 += sA[tg + 3] * ldcg_d(&g_h2d[(tg + 3) * 256 + tid]);
            }
            sg[tid] = (a0 + a1) + (a2 + a3);
        }
        __syncthreads();
        {
            int h = tid & 31, part = tid >> 5;
            double a0 = 0.0, a1 = 0.0, a2 = 0.0, a3 = 0.0;
            #pragma unroll
            for (int m = 0; m < 32; m += 4) {
                a0 += w3d[h * 257 + part + 8 * (m + 0)] * sg[part + 8 * (m + 0)];
                a1 += w3d[h * 257 + part + 8 * (m + 1)] * sg[part + 8 * (m + 1)];
                a2 += w3d[h * 257 + part + 8 * (m + 2)] * sg[part + 8 * (m + 2)];
                a3 += w3d[h * 257 + part + 8 * (m + 3)] * sg[part + 8 * (m + 3)];
            }
            sred[part * 32 + h] = (a0 + a1) + (a2 + a3);
        }
        __syncthreads();
        if (tid < 32) {
            double u = 0.0;
            #pragma unroll
            for (int p = 0; p < 8; p++) u += sred[p * 32 + tid];
            double W = sW[dblk * 130 + hbase + tid];
            g_resP[cta * 32 + tid] = sls[1 + dblk] * W + stp[tid] * u;
        }
        grid_bar(++ep, tid);

        // ---- combine partials (fixed order) and Heun update (redundant per CTA) ----
        if (tid < 128) {
            double k0 = 0.0, k1v = 0.0, k2v = 0.0, k3v = 0.0;
            #pragma unroll
            for (int dd = 0; dd < 16; dd += 4) {
                k0  += ldcg_d(&g_resP[(dd + 0) * 128 + tid]);
                k1v += ldcg_d(&g_resP[(dd + 1) * 128 + tid]);
                k2v += ldcg_d(&g_resP[(dd + 2) * 128 + tid]);
                k3v += ldcg_d(&g_resP[(dd + 3) * 128 + tid]);
            }
            double kv = (k0 + k1v) + (k2v + k3v);
            if ((ev & 1) == 0) {
                sk1[tid] = kv;
                sy[tid] = syb[tid] + dt * kv;        // midpoint input for k2
            } else {
                double yn = syb[tid] + 0.5 * dt * (sk1[tid] + kv);
                syb[tid] = yn;
                sy[tid] = yn;
            }
        }
        __syncthreads();
    }

    // ---- classification head: softmax(y @ l2_w + l2_b), CTA 0 only ----
    if (cta == 0) {
        if (tid < 10) {
            double z = (double)l2_b[tid];
            for (int k = 0; k < 128; k++) z += syb[k] * (double)l2_w[k * 10 + tid];
            sred[tid] = z;
        }
        __syncthreads();
        if (tid == 0) {
            double mx = sred[0];
            for (int j = 1; j < 10; j++) mx = fmax(mx, sred[j]);
            double ex[10]; double ssum = 0.0;
            for (int j = 0; j < 10; j++) { ex[j] = exp(sred[j] - mx); ssum += ex[j]; }
            for (int j = 0; j < 10; j++) out[j] = (float)(ex[j] / ssum);
        }
    }
}

extern "C" void kernel_launch(void* const* d_in, const int* in_sizes, int n_in,
                              void* d_out, int out_size) {
    // ---- assumption-free input resolution by element count ----
    const float *ts = 0, *logsig = 0, *x0 = 0, *l1_b = 0, *w1 = 0, *w2 = 0,
                *w3 = 0, *l2_w = 0, *l2_b = 0;
    const float *c20[2] = {0, 0};   // 2048-sized candidates {l1_w, b3}
    const float *c25[2] = {0, 0};   // 256-sized candidates  {b1, b2}
    int n20 = 0, n25 = 0;
    for (int i = 0; i < n_in; i++) {
        const float* p = (const float*)d_in[i];
        switch (in_sizes[i]) {
            case T_N:      if (!ts) ts = p; break;           // ts / intervals (identical)
            case 27400000: logsig = p; break;
            case 16:       x0 = p; break;
            case 32768:    w1 = p; break;
            case 65536:    w2 = p; break;
            case 524288:   w3 = p; break;
            case 128:      l1_b = p; break;
            case 1280:     l2_w = p; break;
            case 10:       l2_b = p; break;
            case 2048:     if (n20 < 2) c20[n20++] = p; break;
            case 256:      if (n25 < 2) c25[n25++] = p; break;
            default: break;
        }
    }
    if (n20 == 1) c20[1] = c20[0];
    if (n25 == 1) c25[1] = c25[0];
    float* out = (float*)d_out;

    cudaFuncSetAttribute(cde_kernel, cudaFuncAttributeMaxDynamicSharedMemorySize,
                         SMEM_BYTES);

    prep_kernel<<<NEVAL + 2, 256>>>(ts, logsig, c20[0], c20[1], c25[0], c25[1]);
    cde_kernel<<<G, TPB, SMEM_BYTES>>>(ts, x0, c20[0], c20[1], l1_b, w1,
                                       c25[0], c25[1], w2, w3, l2_w, l2_b, out);
}